// round 16
// baseline (speedup 1.0000x reference)
// Round 16: r15's bulk-copy mbarrier pipeline (proven −540us) combined with r12's
// per-(head,batch) partition: 16 clusters x 8 CTAs, 4x less matvec per CTA. The r12
// regression was caused by barrier.cluster round-trip scaling — that barrier is gone;
// mbarrier sync cost is cluster-count independent and NBUF=4 absorbs skew.
#include <cuda_runtime.h>
#include <math.h>
#include <stdint.h>

#define BB 4
#define SS 2048
#define DD 1024
#define NH 4
#define DH 256
#define KK 4
#define NSLICE 8
#define NBUF 4

typedef unsigned long long u64;

// ---------------- scratch (static device arrays; no allocation) ----------------
__device__ float g_xconv[BB * SS * DD];            // 33.5M floats
__device__ float g_gates[SS * NH * 4 * BB * DH];   // [t][h][g][b][e]
__device__ float g_yout [BB * SS * NH * DH];       // [b][t][h][e]

// ---------------- helpers ----------------
__device__ __forceinline__ u64 pk2(float a, float b) {
    u64 r; asm("mov.b64 %0,{%1,%2};" : "=l"(r) : "f"(a), "f"(b)); return r;
}
__device__ __forceinline__ u64 f2fma(u64 a, u64 b, u64 c) {
    u64 d; asm("fma.rn.f32x2 %0,%1,%2,%3;" : "=l"(d) : "l"(a), "l"(b), "l"(c)); return d;
}
__device__ __forceinline__ float f2lo(u64 v) { return __uint_as_float((unsigned)v); }
__device__ __forceinline__ float f2hi(u64 v) { return __uint_as_float((unsigned)(v >> 32)); }
__device__ __forceinline__ uint32_t smem_u32(const void* p) {
    uint32_t a;
    asm("{ .reg .u64 t; cvta.to.shared.u64 t, %1; cvt.u32.u64 %0, t; }" : "=r"(a) : "l"(p));
    return a;
}
__device__ __forceinline__ uint32_t mapa_u32(uint32_t local, int rank) {
    uint32_t r;
    asm("mapa.shared::cluster.u32 %0, %1, %2;" : "=r"(r) : "r"(local), "r"(rank));
    return r;
}
__device__ __forceinline__ void mbar_init(uint32_t a, unsigned cnt) {
    asm volatile("mbarrier.init.shared.b64 [%0], %1;" :: "r"(a), "r"(cnt) : "memory");
}
__device__ __forceinline__ void mbar_arm_tx(uint32_t a, unsigned tx) {
    asm volatile("mbarrier.arrive.expect_tx.shared.b64 _, [%0], %1;" :: "r"(a), "r"(tx) : "memory");
}
__device__ __forceinline__ void mbar_wait(uint32_t a, unsigned parity) {
    unsigned done;
    asm volatile(
        "{\n\t.reg .pred p;\n\t"
        "mbarrier.try_wait.parity.acquire.cluster.shared::cta.b64 p, [%1], %2;\n\t"
        "selp.b32 %0, 1, 0, p;\n\t}"
        : "=r"(done) : "r"(a), "r"(parity) : "memory");
    while (!done) {
        asm volatile(
            "{\n\t.reg .pred p;\n\t"
            "mbarrier.try_wait.parity.acquire.cluster.shared::cta.b64 p, [%1], %2, 0x989680;\n\t"
            "selp.b32 %0, 1, 0, p;\n\t}"
            : "=r"(done) : "r"(a), "r"(parity) : "memory");
    }
}
__device__ __forceinline__ void bulk_copy_cluster(uint32_t dst, uint32_t src,
                                                  unsigned bytes, uint32_t rmbar) {
    asm volatile(
        "cp.async.bulk.shared::cluster.shared::cta.mbarrier::complete_tx::bytes "
        "[%0], [%1], %2, [%3];"
        :: "r"(dst), "r"(src), "r"(bytes), "r"(rmbar) : "memory");
}
#define FENCE_PROXY_ASYNC() asm volatile("fence.proxy.async.shared::cta;" ::: "memory")
#define CLUSTER_SYNC() do { \
    asm volatile("barrier.cluster.arrive.aligned;" ::: "memory"); \
    asm volatile("barrier.cluster.wait.aligned;" ::: "memory"); } while (0)

// ---------------- causal depthwise conv (K=4) + swish ----------------
__global__ void conv_swish_k(const float* __restrict__ x,
                             const float* __restrict__ ck,
                             const float* __restrict__ cb) {
    int bs = blockIdx.x;
    int b = bs >> 11, s = bs & (SS - 1);
    int q = threadIdx.x;  // d-quad 0..255
    const float4* x4 = (const float4*)x;
    const float4* k4 = (const float4*)ck;
    float4 k0 = k4[0 * (DD / 4) + q];
    float4 k1 = k4[1 * (DD / 4) + q];
    float4 k2 = k4[2 * (DD / 4) + q];
    float4 k3 = k4[3 * (DD / 4) + q];
    float4 acc = ((const float4*)cb)[q];
    int rowq = (b * SS + s) * (DD / 4);
#define CONV_TAP(kk, kv)                                            \
    { int sr = s - 3 + (kk);                                        \
      if (sr >= 0) {                                                \
          float4 xv = x4[(b * SS + sr) * (DD / 4) + q];             \
          acc.x += (kv).x * xv.x; acc.y += (kv).y * xv.y;           \
          acc.z += (kv).z * xv.z; acc.w += (kv).w * xv.w; } }
    CONV_TAP(0, k0) CONV_TAP(1, k1) CONV_TAP(2, k2) CONV_TAP(3, k3)
#undef CONV_TAP
    float4 r;
    r.x = acc.x / (1.f + expf(-acc.x));
    r.y = acc.y / (1.f + expf(-acc.y));
    r.z = acc.z / (1.f + expf(-acc.z));
    r.w = acc.w / (1.f + expf(-acc.w));
    ((float4*)g_xconv)[rowq + q] = r;
}

// ---------------- gate GEMMs: gates[t][h][g][b][e]  (packed f32x2 FMA) ----------------
__global__ void __launch_bounds__(256, 1)
gates_gemm_k(const float* __restrict__ x,
             const float* __restrict__ w_i, const float* __restrict__ w_f,
             const float* __restrict__ w_z, const float* __restrict__ w_o) {
    int h = blockIdx.z >> 2, g = blockIdx.z & 3;
    int b = blockIdx.y >> 1, eh = blockIdx.y & 1;
    int sch = blockIdx.x;
    const float* in = (g < 2) ? g_xconv : x;
    const float* W = (g == 0) ? w_i : (g == 1) ? w_f : (g == 2) ? w_z : w_o;

    int tid = threadIdx.x, lane = tid & 31, wid = tid >> 5;
    int el = wid * 16 + (lane & 15);
    int dh = lane >> 4;
    int eg = eh * 128 + el;
    int dbase = dh * 128;

    ulonglong2 wq[32];
#pragma unroll
    for (int j = 0; j < 32; j++) {
        const float* p = W + (size_t)(h * DH + dbase + 4 * j) * DH + eg;
        wq[j].x = pk2(p[0], p[DH]);
        wq[j].y = pk2(p[2 * DH], p[3 * DH]);
    }

    __shared__ __align__(16) float As[32][256];

    for (int tt = 0; tt < 4; tt++) {
        int s0 = (sch * 4 + tt) * 32;
        for (int l = tid; l < 32 * 64; l += 256) {
            int r = l >> 6, q = l & 63;
            ((float4*)As[r])[q] =
                ((const float4*)(in + (size_t)(b * SS + s0 + r) * DD + h * DH))[q];
        }
        __syncthreads();
#pragma unroll 1
        for (int r = 0; r < 32; r++) {
            u64 al = 0, ah = 0;
#pragma unroll
            for (int j = 0; j < 32; j++) {
                ulonglong2 av = *(const ulonglong2*)&As[r][dbase + 4 * j];
                al = f2fma(wq[j].x, av.x, al);
                ah = f2fma(wq[j].y, av.y, ah);
            }
            float sum = (f2lo(al) + f2hi(al)) + (f2lo(ah) + f2hi(ah));
            sum += __shfl_xor_sync(0xffffffffu, sum, 16);
            if (dh == 0)
                g_gates[(size_t)(((s0 + r) * NH + h) * 4 + g) * (BB * DH) + b * DH + eg] = sum;
        }
        __syncthreads();
    }
}

// ---------------- recurrence: 16 clusters (one per (h,b)), bulk-copy pipeline ----------
__global__ void __launch_bounds__(256, 1) __cluster_dims__(NSLICE, 1, 1)
rec_k(const float* __restrict__ Wr, const float* __restrict__ rb) {
    int hb = blockIdx.y;            // h*BB + b
    int h = hb >> 2, b = hb & 3;
    int si = blockIdx.x;            // cluster rank = e-slice
    int tid = threadIdx.x, lane = tid & 31, wid = tid >> 5;
    int g = wid & 3, ehi = wid >> 2;
    int dh = lane >> 4;
    int e = ehi * 16 + (lane & 15);
    int eg = si * 32 + e;
    int dbase = dh * 128;

    // packed recurrent weights: W[h][d][g][eg], pairs (d,d+1); stride 4*DH per d
    ulonglong2 wq[32];
#pragma unroll
    for (int j = 0; j < 32; j++) {
        const float* p = Wr + (size_t)((h * DH + dbase + 4 * j) * 4 + g) * DH + eg;
        wq[j].x = pk2(p[0], p[4 * DH]);
        wq[j].y = pk2(p[8 * DH], p[12 * DH]);
    }

    // state threads: tid<32 -> e within slice
    int se = lane;
    int seg = si * 32 + se;
    float bI = 0, bF = 0, bZ = 0, bO = 0, c = 0, n = 0, m = 0;
    if (tid < 32) {
        bI = rb[(0 * NH + h) * DH + seg];
        bF = rb[(1 * NH + h) * DH + seg];
        bZ = rb[(2 * NH + h) * DH + seg];
        bO = rb[(3 * NH + h) * DH + seg];
    }

    // y ring: [buf][slice][32] — slice = contiguous 128B block; e-order preserved
    __shared__ __align__(1024) float y_s[NBUF][NSLICE][32];
    __shared__ float raw_s[4][32];
    __shared__ __align__(16) float y_stage[32];       // fresh y slice (128B)
    __shared__ __align__(8) u64 mb[NBUF];             // full[buf] mbarriers

    const unsigned BUFB = NSLICE * 32 * 4;            // 1024 bytes per buffer
    const unsigned TXB = NSLICE * 128;                // 1024 tx bytes per fill

    uint32_t mb0 = smem_u32(&mb[0]);
    if (tid == 0) {
#pragma unroll
        for (int k = 0; k < NBUF; k++) {
            mbar_init(mb0 + 8 * k, 1);
            mbar_arm_tx(mb0 + 8 * k, TXB);
        }
    }
    for (int i = tid; i < (int)(BUFB / 16); i += 256)  // zero buffer 0 (read at t=0)
        ((float4*)&y_s[0][0][0])[i] = make_float4(0.f, 0.f, 0.f, 0.f);
    __syncthreads();
    CLUSTER_SYNC();  // barriers armed + buf0 zeroed everywhere before any pushes

    uint32_t dstB[NSLICE], mbB[NSLICE];
    uint32_t myBlk = smem_u32(&y_s[0][si][0]);
    uint32_t stg = smem_u32(&y_stage[0]);
#pragma unroll
    for (int r = 0; r < NSLICE; r++) {
        dstB[r] = mapa_u32(myBlk, r);
        mbB[r] = mapa_u32(mb0, r);
    }

    const float* gbase = g_gates + (size_t)h * 4 * (BB * DH) + b * DH;
    float* ybase = g_yout + (size_t)(b * SS * NH + h) * DH;

    // software-pipelined gate inputs: preload step 0
    float gI = 0, gF = 0, gZ = 0, gO = 0;
    if (tid < 32) {
        const float* gp = gbase + seg;
        gI = gp[0];
        gF = gp[BB * DH];
        gZ = gp[2 * BB * DH];
        gO = gp[3 * BB * DH];
    }

    unsigned ph = 0;
    float yv = 0.f;

    for (int t = 0; t < SS; t++) {
        int k = t & (NBUF - 1);
        if (t > 0) {
            mbar_wait(mb0 + 8 * k, (ph >> k) & 1u);
            ph ^= 1u << k;
            if (tid == 0) mbar_arm_tx(mb0 + 8 * k, TXB);  // re-arm for t+4 (peers can't
                                                          // push y(t+4) before my y(t+3))
        }

        // 1-batch matvec, packed f32x2; my 128-d window is contiguous & e-ordered
        const float* ybk = &y_s[k][dh * 4][0];
        u64 al = 0, ah = 0;
#pragma unroll
        for (int j = 0; j < 32; j++) {
            ulonglong2 y2 = *(const ulonglong2*)&ybk[4 * j];
            al = f2fma(wq[j].x, y2.x, al);
            ah = f2fma(wq[j].y, y2.y, ah);
        }
        float r0 = (f2lo(al) + f2hi(al)) + (f2lo(ah) + f2hi(ah));
        r0 += __shfl_xor_sync(0xffffffffu, r0, 16);
        if (dh == 0) raw_s[g][e] = r0;
        __syncthreads();

        if (tid < 32) {
            float rI = raw_s[0][se] + gI + bI;
            float rF = raw_s[1][se] + gF + bF;
            float rZ = raw_s[2][se] + gZ + bZ;
            float rO = raw_s[3][se] + gO + bO;

            // consume gates -> issue next step's loads (hidden behind rest of step)
            if (t + 1 < SS) {
                const float* gp = gbase + (size_t)(t + 1) * NH * 4 * (BB * DH) + seg;
                gI = gp[0];
                gF = gp[BB * DH];
                gZ = gp[2 * BB * DH];
                gO = gp[3 * BB * DH];
            }

            // MUFU stabilized update (precision proven r11-r15: rel_err 3.72e-7)
            float lsf = fminf(rF, 0.f) - __logf(1.f + __expf(-fabsf(rF)));
            float lfm = m + lsf;
            float mn = fmaxf(rI, lfm);
            float ig = __expf(rI - mn);
            float fg = __expf(lfm - mn);
            float tz = 1.f - 2.f / (1.f + __expf(2.f * rZ));  // tanh(rZ)
            c = fg * c + ig * tz;
            n = fg * n + ig;
            m = mn;
            yv = (c / n) / (1.f + __expf(-rO));
            y_stage[se] = yv;
        }
        __syncthreads();  // stage complete CTA-wide

        // broadcast my 128B slice to every rank's buf (t+1)&3
        if (tid == 0 && t + 1 < SS) {
            FENCE_PROXY_ASYNC();
            int kn = (t + 1) & (NBUF - 1);
#pragma unroll
            for (int r = 0; r < NSLICE; r++)
                bulk_copy_cluster(dstB[r] + kn * BUFB, stg, 128, mbB[r] + 8 * kn);
        }

        // global y record — off the inter-CTA critical path
        if (tid < 32)
            ybase[(size_t)t * NH * DH + seg] = yv;
    }
    CLUSTER_SYNC();
}

// ---------------- per-head GroupNorm + affine ----------------
__global__ void gnorm_k(const float* __restrict__ gsc,
                        const float* __restrict__ gbi,
                        float* __restrict__ out) {
    int bs = blockIdx.x;
    int b = bs >> 11, s = bs & (SS - 1);
    int lane = threadIdx.x & 31, h = threadIdx.x >> 5;
    const float* yp = g_yout + (size_t)((b * SS + s) * NH + h) * DH;
    float4 v0 = ((const float4*)yp)[lane * 2];
    float4 v1 = ((const float4*)yp)[lane * 2 + 1];
    float sum = v0.x + v0.y + v0.z + v0.w + v1.x + v1.y + v1.z + v1.w;
    float sq = v0.x * v0.x + v0.y * v0.y + v0.z * v0.z + v0.w * v0.w +
               v1.x * v1.x + v1.y * v1.y + v1.z * v1.z + v1.w * v1.w;
#pragma unroll
    for (int o = 16; o; o >>= 1) {
        sum += __shfl_xor_sync(0xffffffffu, sum, o);
        sq += __shfl_xor_sync(0xffffffffu, sq, o);
    }
    float mean = sum * (1.f / DH);
    float var = sq * (1.f / DH) - mean * mean;
    float rs = rsqrtf(var + 1e-6f);
    int dbase = h * DH + lane * 8;
    float4 sc0 = ((const float4*)(gsc + dbase))[0];
    float4 sc1 = ((const float4*)(gsc + dbase))[1];
    float4 bi0 = ((const float4*)(gbi + dbase))[0];
    float4 bi1 = ((const float4*)(gbi + dbase))[1];
    float* op = out + (size_t)(b * SS + s) * DD + dbase;
    float4 o0, o1;
    o0.x = (v0.x - mean) * rs * sc0.x + bi0.x;
    o0.y = (v0.y - mean) * rs * sc0.y + bi0.y;
    o0.z = (v0.z - mean) * rs * sc0.z + bi0.z;
    o0.w = (v0.w - mean) * rs * sc0.w + bi0.w;
    o1.x = (v1.x - mean) * rs * sc1.x + bi1.x;
    o1.y = (v1.y - mean) * rs * sc1.y + bi1.y;
    o1.z = (v1.z - mean) * rs * sc1.z + bi1.z;
    o1.w = (v1.w - mean) * rs * sc1.w + bi1.w;
    ((float4*)op)[0] = o0;
    ((float4*)op)[1] = o1;
}

// ---------------- launch ----------------
extern "C" void kernel_launch(void* const* d_in, const int* in_sizes, int n_in,
                              void* d_out, int out_size) {
    const float* x   = (const float*)d_in[0];
    const float* ck  = (const float*)d_in[1];
    const float* cb  = (const float*)d_in[2];
    const float* w_i = (const float*)d_in[3];
    const float* w_f = (const float*)d_in[4];
    const float* w_z = (const float*)d_in[5];
    const float* w_o = (const float*)d_in[6];
    const float* wr  = (const float*)d_in[7];
    const float* rb  = (const float*)d_in[8];
    const float* gsc = (const float*)d_in[9];
    const float* gbi = (const float*)d_in[10];
    float* out = (float*)d_out;

    conv_swish_k<<<BB * SS, 256>>>(x, ck, cb);
    dim3 gg(16, 8, 16);
    gates_gemm_k<<<gg, 256>>>(x, w_i, w_f, w_z, w_o);
    dim3 gr(NSLICE, NH * BB);  // 16 clusters of 8 CTAs: one per (head, batch)
    rec_k<<<gr, 256>>>(wr, rb);
    gnorm_k<<<BB * SS, 128>>>(gsc, gbi, out);
}